// round 6
// baseline (speedup 1.0000x reference)
#include <cuda_runtime.h>
#include <cuda_fp16.h>
#include <cuda_bf16.h>

#define N_NODES 100000
#define N_EDGES 1600000
#define IN_F 128
#define OUT_F 48
#define H_PAD 64   // fp16 elems per padded h row (128 bytes = 1 cache line)
#define NBLK_SCAN ((N_NODES + 1023) / 1024)   // 98

struct __align__(8) DC { float sdst; int cur; };

// Scratch (__device__ globals; zero-initialized at load; no allocations allowed)
__device__ float  g_ssrc[N_NODES];                    // h . w_src
__device__ DC     g_dc[N_NODES];                      // {h.w_dst, scatter cursor}
__device__ __half g_hh[(size_t)N_NODES * H_PAD];      // projected features (fp16, 128B rows)
__device__ int    g_cnt[N_NODES];                     // degree by dst (zero at entry!)
__device__ int    g_off[N_NODES];                     // CSR offsets
__device__ unsigned long long g_state[NBLK_SCAN];     // lookback state (zero at entry!)
__device__ unsigned long long g_edge[N_EDGES];        // packed {src, ex}

// ---------------------------------------------------------------------------
// GEMM + dst histogram.
// ---------------------------------------------------------------------------
__global__ void __launch_bounds__(128) k_gemm(
    const float* __restrict__ feat, const float* __restrict__ Ww,
    const float* __restrict__ Wb, const float* __restrict__ attnw,
    const int* __restrict__ dst)
{
    // --- histogram of dst (grid-stride, no-return atomics drain under FMAs) ---
    {
        int gsz = gridDim.x * 128;
        for (int e = blockIdx.x * 128 + threadIdx.x; e < N_EDGES; e += gsz)
            atomicAdd(&g_cnt[__ldg(dst + e)], 1);
    }

    __shared__ unsigned long long sWp[IN_F][OUT_F / 2];
    __shared__ float sb[OUT_F], sws[OUT_F], swd[OUT_F];

    int tid = threadIdx.x;
    for (int i = tid; i < IN_F * (OUT_F / 2); i += 128) {
        int k  = i / (OUT_F / 2);
        int jj = i % (OUT_F / 2);
        float lo = Ww[(2 * jj) * IN_F + k];
        float hi = Ww[(2 * jj + 1) * IN_F + k];
        unsigned long long p;
        asm("mov.b64 %0, {%1, %2};" : "=l"(p) : "f"(lo), "f"(hi));
        sWp[k][jj] = p;
    }
    if (tid < OUT_F) {
        sb[tid]  = Wb[tid];
        sws[tid] = attnw[tid];
        swd[tid] = attnw[OUT_F + tid];
    }
    __syncthreads();

    long n0 = (long)blockIdx.x * 256 + tid;
    long n1 = n0 + 128;
    bool v0 = n0 < N_NODES, v1 = n1 < N_NODES;
    const float4* r0 = (const float4*)(feat + (v0 ? n0 : 0) * IN_F);
    const float4* r1 = (const float4*)(feat + (v1 ? n1 : 0) * IN_F);

    unsigned long long a0[OUT_F / 2], a1[OUT_F / 2];
#pragma unroll
    for (int jj = 0; jj < OUT_F / 2; jj++) {
        unsigned long long p;
        asm("mov.b64 %0, {%1, %2};" : "=l"(p) : "f"(sb[2 * jj]), "f"(sb[2 * jj + 1]));
        a0[jj] = p;
        a1[jj] = p;
    }

#pragma unroll 2
    for (int k4 = 0; k4 < IN_F / 4; k4++) {
        float4 f0 = r0[k4];
        float4 f1 = r1[k4];
        float fs0[4] = {f0.x, f0.y, f0.z, f0.w};
        float fs1[4] = {f1.x, f1.y, f1.z, f1.w};
#pragma unroll
        for (int u = 0; u < 4; u++) {
            unsigned long long ff0, ff1;
            asm("mov.b64 %0, {%1, %1};" : "=l"(ff0) : "f"(fs0[u]));
            asm("mov.b64 %0, {%1, %1};" : "=l"(ff1) : "f"(fs1[u]));
            int k = 4 * k4 + u;
#pragma unroll
            for (int jj = 0; jj < OUT_F / 2; jj++) {
                unsigned long long w = sWp[k][jj];
                asm("fma.rn.f32x2 %0, %1, %2, %0;" : "+l"(a0[jj]) : "l"(ff0), "l"(w));
                asm("fma.rn.f32x2 %0, %1, %2, %0;" : "+l"(a1[jj]) : "l"(ff1), "l"(w));
            }
        }
    }

    if (v0) {
        float s1 = 0.0f, s2 = 0.0f;
        unsigned hh[OUT_F / 2];
#pragma unroll
        for (int jj = 0; jj < OUT_F / 2; jj++) {
            float lo, hi;
            asm("mov.b64 {%0, %1}, %2;" : "=f"(lo), "=f"(hi) : "l"(a0[jj]));
            s1 += lo * sws[2 * jj] + hi * sws[2 * jj + 1];
            s2 += lo * swd[2 * jj] + hi * swd[2 * jj + 1];
            __half2 h2 = __floats2half2_rn(lo, hi);
            hh[jj] = *(unsigned*)&h2;
        }
        uint4* hr = (uint4*)(g_hh + (size_t)n0 * H_PAD);
#pragma unroll
        for (int i = 0; i < 6; i++)
            hr[i] = make_uint4(hh[4 * i], hh[4 * i + 1], hh[4 * i + 2], hh[4 * i + 3]);
        hr[6] = make_uint4(0, 0, 0, 0);
        hr[7] = make_uint4(0, 0, 0, 0);
        g_ssrc[n0] = s1;
        g_dc[n0].sdst = s2;
    }
    if (v1) {
        float s1 = 0.0f, s2 = 0.0f;
        unsigned hh[OUT_F / 2];
#pragma unroll
        for (int jj = 0; jj < OUT_F / 2; jj++) {
            float lo, hi;
            asm("mov.b64 {%0, %1}, %2;" : "=f"(lo), "=f"(hi) : "l"(a1[jj]));
            s1 += lo * sws[2 * jj] + hi * sws[2 * jj + 1];
            s2 += lo * swd[2 * jj] + hi * swd[2 * jj + 1];
            __half2 h2 = __floats2half2_rn(lo, hi);
            hh[jj] = *(unsigned*)&h2;
        }
        uint4* hr = (uint4*)(g_hh + (size_t)n1 * H_PAD);
#pragma unroll
        for (int i = 0; i < 6; i++)
            hr[i] = make_uint4(hh[4 * i], hh[4 * i + 1], hh[4 * i + 2], hh[4 * i + 3]);
        hr[6] = make_uint4(0, 0, 0, 0);
        hr[7] = make_uint4(0, 0, 0, 0);
        g_ssrc[n1] = s1;
        g_dc[n1].sdst = s2;
    }
}

// ---------------------------------------------------------------------------
// Single-pass exclusive scan of g_cnt -> g_off / g_dc[].cur (decoupled lookback).
// ---------------------------------------------------------------------------
__global__ void __launch_bounds__(1024) k_scan()
{
    __shared__ int wsum[32];
    __shared__ int s_prefix;
    int tid = threadIdx.x, bid = blockIdx.x;
    int gid = bid * 1024 + tid;
    int lane = tid & 31, wid = tid >> 5;
    int x = (gid < N_NODES) ? g_cnt[gid] : 0;
    int incl = x;
#pragma unroll
    for (int o = 1; o < 32; o <<= 1) {
        int y = __shfl_up_sync(0xFFFFFFFFu, incl, o);
        if (lane >= o) incl += y;
    }
    if (lane == 31) wsum[wid] = incl;
    __syncthreads();
    if (wid == 0) {
        int v = wsum[lane];
#pragma unroll
        for (int o = 1; o < 32; o <<= 1) {
            int y = __shfl_up_sync(0xFFFFFFFFu, v, o);
            if (lane >= o) v += y;
        }
        wsum[lane] = v;
    }
    __syncthreads();
    int wofs = (wid > 0) ? wsum[wid - 1] : 0;
    int total = wsum[31];

    if (tid == 0) {
        if (bid == 0) {
            atomicExch(&g_state[0], (2ULL << 62) | (unsigned)total);
            s_prefix = 0;
        } else {
            atomicExch(&g_state[bid], (1ULL << 62) | (unsigned)total);
            int run = 0;
            int j = bid - 1;
            while (true) {
                unsigned long long v = atomicAdd(&g_state[j], 0ULL);
                unsigned f = (unsigned)(v >> 62);
                if (f == 0) { __nanosleep(20); continue; }
                run += (int)(v & 0xFFFFFFFFULL);
                if (f == 2) break;
                j--;
            }
            atomicExch(&g_state[bid], (2ULL << 62) | (unsigned)(run + total));
            s_prefix = run;
        }
    }
    __syncthreads();
    if (gid < N_NODES) {
        int o = s_prefix + wofs + incl - x;
        g_off[gid] = o;
        g_dc[gid].cur = o;
    }
}

// ---------------------------------------------------------------------------
// Scatter: 4 edges/thread (int4 loads, MLP=4 on random gathers);
// sdst and cursor share one 8B struct -> same L2 sector.
// ---------------------------------------------------------------------------
__global__ void __launch_bounds__(256) k_scatter(
    const int* __restrict__ src, const int* __restrict__ dst,
    const float* __restrict__ attnb)
{
    int i = blockIdx.x * blockDim.x + threadIdx.x;
    int e0 = i * 4;
    if (e0 >= N_EDGES) return;
    float b = attnb[0];

    int4 s4 = *(const int4*)(src + e0);
    int4 d4 = *(const int4*)(dst + e0);

    float ss0 = g_ssrc[s4.x], ss1 = g_ssrc[s4.y], ss2 = g_ssrc[s4.z], ss3 = g_ssrc[s4.w];
    float sd0 = g_dc[d4.x].sdst, sd1 = g_dc[d4.y].sdst, sd2 = g_dc[d4.z].sdst, sd3 = g_dc[d4.w].sdst;

    float v0 = ss0 + sd0 + b, v1 = ss1 + sd1 + b, v2 = ss2 + sd2 + b, v3 = ss3 + sd3 + b;
    v0 = (v0 > 0.0f) ? v0 : 0.2f * v0;
    v1 = (v1 > 0.0f) ? v1 : 0.2f * v1;
    v2 = (v2 > 0.0f) ? v2 : 0.2f * v2;
    v3 = (v3 > 0.0f) ? v3 : 0.2f * v3;
    float ex0 = __expf(v0), ex1 = __expf(v1), ex2 = __expf(v2), ex3 = __expf(v3);

    int p0 = atomicAdd(&g_dc[d4.x].cur, 1);
    int p1 = atomicAdd(&g_dc[d4.y].cur, 1);
    int p2 = atomicAdd(&g_dc[d4.z].cur, 1);
    int p3 = atomicAdd(&g_dc[d4.w].cur, 1);
    g_edge[p0] = ((unsigned long long)(unsigned)s4.x << 32) | __float_as_uint(ex0);
    g_edge[p1] = ((unsigned long long)(unsigned)s4.y << 32) | __float_as_uint(ex1);
    g_edge[p2] = ((unsigned long long)(unsigned)s4.z << 32) | __float_as_uint(ex2);
    g_edge[p3] = ((unsigned long long)(unsigned)s4.w << 32) | __float_as_uint(ex3);
}

// ---------------------------------------------------------------------------
// Gather: 8 threads/node; lane t loads uint4 #t of the padded 128B h row
// (one cache line per edge per group). 4-edge unroll -> MLP=4 on the random
// h-line loads. Lanes 0-5 own 8 outputs each; lanes 6-7 do invariant restores.
// ---------------------------------------------------------------------------
__device__ __forceinline__ void acc8(float* a, uint4 w, float ex)
{
    float2 f;
    f = __half22float2(*(__half2*)&w.x); a[0] = fmaf(f.x, ex, a[0]); a[1] = fmaf(f.y, ex, a[1]);
    f = __half22float2(*(__half2*)&w.y); a[2] = fmaf(f.x, ex, a[2]); a[3] = fmaf(f.y, ex, a[3]);
    f = __half22float2(*(__half2*)&w.z); a[4] = fmaf(f.x, ex, a[4]); a[5] = fmaf(f.y, ex, a[5]);
    f = __half22float2(*(__half2*)&w.w); a[6] = fmaf(f.x, ex, a[6]); a[7] = fmaf(f.y, ex, a[7]);
}

__global__ void __launch_bounds__(256) k_gather(float* __restrict__ out)
{
    int gt = blockIdx.x * blockDim.x + threadIdx.x;
    int n = gt >> 3;
    int t = gt & 7;
    if (n >= N_NODES) return;
    int start = g_off[n];
    int deg = g_cnt[n];

    const uint4* H = (const uint4*)g_hh;  // padded row = 8 uint4 (128B)

    float acc[8];
#pragma unroll
    for (int i = 0; i < 8; i++) acc[i] = 0.0f;
    float den = 0.0f;

    int k = 0;
    for (; k + 4 <= deg; k += 4) {
        unsigned long long p0 = __ldg(&g_edge[start + k]);
        unsigned long long p1 = __ldg(&g_edge[start + k + 1]);
        unsigned long long p2 = __ldg(&g_edge[start + k + 2]);
        unsigned long long p3 = __ldg(&g_edge[start + k + 3]);
        float ex0 = __uint_as_float((unsigned)p0);
        float ex1 = __uint_as_float((unsigned)p1);
        float ex2 = __uint_as_float((unsigned)p2);
        float ex3 = __uint_as_float((unsigned)p3);
        int s0 = (int)(p0 >> 32), s1 = (int)(p1 >> 32);
        int s2 = (int)(p2 >> 32), s3 = (int)(p3 >> 32);
        uint4 w0 = __ldg(&H[s0 * 8 + t]);
        uint4 w1 = __ldg(&H[s1 * 8 + t]);
        uint4 w2 = __ldg(&H[s2 * 8 + t]);
        uint4 w3 = __ldg(&H[s3 * 8 + t]);
        den += (ex0 + ex1) + (ex2 + ex3);
        acc8(acc, w0, ex0);
        acc8(acc, w1, ex1);
        acc8(acc, w2, ex2);
        acc8(acc, w3, ex3);
    }
    for (; k < deg; k++) {
        unsigned long long p0 = __ldg(&g_edge[start + k]);
        float ex0 = __uint_as_float((unsigned)p0);
        int s0 = (int)(p0 >> 32);
        uint4 w0 = __ldg(&H[s0 * 8 + t]);
        den += ex0;
        acc8(acc, w0, ex0);
    }

    if (t < 6) {
        float inv = (deg > 0) ? 1.0f / den : 0.0f;
        float4* op = (float4*)(out + (size_t)n * OUT_F + t * 8);
        op[0] = make_float4(acc[0] * inv, acc[1] * inv, acc[2] * inv, acc[3] * inv);
        op[1] = make_float4(acc[4] * inv, acc[5] * inv, acc[6] * inv, acc[7] * inv);
    }
    // Restore zero-invariants for the next graph replay (warp-safe: the
    // g_cnt load above is issued for the whole warp before any lane stores).
    if (t == 6) g_cnt[n] = 0;
    if (t == 7 && n < NBLK_SCAN) g_state[n] = 0ULL;
}

// ---------------------------------------------------------------------------
extern "C" void kernel_launch(void* const* d_in, const int* in_sizes, int n_in,
                              void* d_out, int out_size)
{
    const float* feat  = (const float*)d_in[0];
    const float* Ww    = (const float*)d_in[1];
    const float* Wb    = (const float*)d_in[2];
    const float* attnw = (const float*)d_in[3];
    const float* attnb = (const float*)d_in[4];
    const int*   src   = (const int*)d_in[5];
    const int*   dst   = (const int*)d_in[6];
    float* out = (float*)d_out;

    k_gemm<<<(N_NODES + 255) / 256, 128>>>(feat, Ww, Wb, attnw, dst);
    k_scan<<<NBLK_SCAN, 1024>>>();
    k_scatter<<<(N_EDGES / 4 + 255) / 256, 256>>>(src, dst, attnb);
    k_gather<<<(N_NODES * 8 + 255) / 256, 256>>>(out);
}

// round 7
// speedup vs baseline: 1.1554x; 1.1554x over previous
#include <cuda_runtime.h>
#include <cuda_fp16.h>
#include <cuda_bf16.h>

#define N_NODES 100000
#define N_EDGES 1600000
#define IN_F 128
#define OUT_F 48
#define NBLK_SCAN ((N_NODES + 1023) / 1024)   // 98

// Scratch (__device__ globals; zero-initialized at load; no allocations allowed)
__device__ float  g_ssrc[N_NODES];                    // h . w_src
__device__ float  g_sdst[N_NODES];                    // h . w_dst
__device__ __half g_hh[(size_t)N_NODES * OUT_F];      // projected features (fp16, 96B rows)
__device__ int    g_cnt[N_NODES];                     // degree by dst (zero at entry!)
__device__ int    g_off[N_NODES];                     // CSR offsets
__device__ int    g_cursor[N_NODES];                  // scatter cursors
__device__ unsigned long long g_state[NBLK_SCAN];     // lookback state (zero at entry!)
__device__ unsigned long long g_edge[N_EDGES];        // packed {src, ex}

// ---------------------------------------------------------------------------
// GEMM + dst histogram.
// ---------------------------------------------------------------------------
__global__ void __launch_bounds__(128) k_gemm(
    const float* __restrict__ feat, const float* __restrict__ Ww,
    const float* __restrict__ Wb, const float* __restrict__ attnw,
    const int* __restrict__ dst)
{
    // --- histogram of dst (grid-stride, no-return atomics drain under FMAs) ---
    {
        int gsz = gridDim.x * 128;
        for (int e = blockIdx.x * 128 + threadIdx.x; e < N_EDGES; e += gsz)
            atomicAdd(&g_cnt[dst[e]], 1);
    }

    __shared__ unsigned long long sWp[IN_F][OUT_F / 2];
    __shared__ float sb[OUT_F], sws[OUT_F], swd[OUT_F];

    int tid = threadIdx.x;
    for (int i = tid; i < IN_F * (OUT_F / 2); i += 128) {
        int k  = i / (OUT_F / 2);
        int jj = i % (OUT_F / 2);
        float lo = Ww[(2 * jj) * IN_F + k];
        float hi = Ww[(2 * jj + 1) * IN_F + k];
        unsigned long long p;
        asm("mov.b64 %0, {%1, %2};" : "=l"(p) : "f"(lo), "f"(hi));
        sWp[k][jj] = p;
    }
    if (tid < OUT_F) {
        sb[tid]  = Wb[tid];
        sws[tid] = attnw[tid];
        swd[tid] = attnw[OUT_F + tid];
    }
    __syncthreads();

    long n0 = (long)blockIdx.x * 256 + tid;
    long n1 = n0 + 128;
    bool v0 = n0 < N_NODES, v1 = n1 < N_NODES;
    const float4* r0 = (const float4*)(feat + (v0 ? n0 : 0) * IN_F);
    const float4* r1 = (const float4*)(feat + (v1 ? n1 : 0) * IN_F);

    unsigned long long a0[OUT_F / 2], a1[OUT_F / 2];
#pragma unroll
    for (int jj = 0; jj < OUT_F / 2; jj++) {
        unsigned long long p;
        asm("mov.b64 %0, {%1, %2};" : "=l"(p) : "f"(sb[2 * jj]), "f"(sb[2 * jj + 1]));
        a0[jj] = p;
        a1[jj] = p;
    }

#pragma unroll 2
    for (int k4 = 0; k4 < IN_F / 4; k4++) {
        float4 f0 = r0[k4];
        float4 f1 = r1[k4];
        float fs0[4] = {f0.x, f0.y, f0.z, f0.w};
        float fs1[4] = {f1.x, f1.y, f1.z, f1.w};
#pragma unroll
        for (int u = 0; u < 4; u++) {
            unsigned long long ff0, ff1;
            asm("mov.b64 %0, {%1, %1};" : "=l"(ff0) : "f"(fs0[u]));
            asm("mov.b64 %0, {%1, %1};" : "=l"(ff1) : "f"(fs1[u]));
            int k = 4 * k4 + u;
#pragma unroll
            for (int jj = 0; jj < OUT_F / 2; jj++) {
                unsigned long long w = sWp[k][jj];
                asm("fma.rn.f32x2 %0, %1, %2, %0;" : "+l"(a0[jj]) : "l"(ff0), "l"(w));
                asm("fma.rn.f32x2 %0, %1, %2, %0;" : "+l"(a1[jj]) : "l"(ff1), "l"(w));
            }
        }
    }

    if (v0) {
        float s1 = 0.0f, s2 = 0.0f;
        unsigned hh[OUT_F / 2];
#pragma unroll
        for (int jj = 0; jj < OUT_F / 2; jj++) {
            float lo, hi;
            asm("mov.b64 {%0, %1}, %2;" : "=f"(lo), "=f"(hi) : "l"(a0[jj]));
            s1 += lo * sws[2 * jj] + hi * sws[2 * jj + 1];
            s2 += lo * swd[2 * jj] + hi * swd[2 * jj + 1];
            __half2 h2 = __floats2half2_rn(lo, hi);
            hh[jj] = *(unsigned*)&h2;
        }
        uint4* hr = (uint4*)(g_hh + (size_t)n0 * OUT_F);
#pragma unroll
        for (int i = 0; i < 6; i++)
            hr[i] = make_uint4(hh[4 * i], hh[4 * i + 1], hh[4 * i + 2], hh[4 * i + 3]);
        g_ssrc[n0] = s1;
        g_sdst[n0] = s2;
    }
    if (v1) {
        float s1 = 0.0f, s2 = 0.0f;
        unsigned hh[OUT_F / 2];
#pragma unroll
        for (int jj = 0; jj < OUT_F / 2; jj++) {
            float lo, hi;
            asm("mov.b64 {%0, %1}, %2;" : "=f"(lo), "=f"(hi) : "l"(a1[jj]));
            s1 += lo * sws[2 * jj] + hi * sws[2 * jj + 1];
            s2 += lo * swd[2 * jj] + hi * swd[2 * jj + 1];
            __half2 h2 = __floats2half2_rn(lo, hi);
            hh[jj] = *(unsigned*)&h2;
        }
        uint4* hr = (uint4*)(g_hh + (size_t)n1 * OUT_F);
#pragma unroll
        for (int i = 0; i < 6; i++)
            hr[i] = make_uint4(hh[4 * i], hh[4 * i + 1], hh[4 * i + 2], hh[4 * i + 3]);
        g_ssrc[n1] = s1;
        g_sdst[n1] = s2;
    }
}

// ---------------------------------------------------------------------------
// Single-pass exclusive scan of g_cnt -> g_off/g_cursor (decoupled lookback).
// ---------------------------------------------------------------------------
__global__ void __launch_bounds__(1024) k_scan()
{
    __shared__ int wsum[32];
    __shared__ int s_prefix;
    int tid = threadIdx.x, bid = blockIdx.x;
    int gid = bid * 1024 + tid;
    int lane = tid & 31, wid = tid >> 5;
    int x = (gid < N_NODES) ? g_cnt[gid] : 0;
    int incl = x;
#pragma unroll
    for (int o = 1; o < 32; o <<= 1) {
        int y = __shfl_up_sync(0xFFFFFFFFu, incl, o);
        if (lane >= o) incl += y;
    }
    if (lane == 31) wsum[wid] = incl;
    __syncthreads();
    if (wid == 0) {
        int v = wsum[lane];
#pragma unroll
        for (int o = 1; o < 32; o <<= 1) {
            int y = __shfl_up_sync(0xFFFFFFFFu, v, o);
            if (lane >= o) v += y;
        }
        wsum[lane] = v;
    }
    __syncthreads();
    int wofs = (wid > 0) ? wsum[wid - 1] : 0;
    int total = wsum[31];

    if (tid == 0) {
        if (bid == 0) {
            atomicExch(&g_state[0], (2ULL << 62) | (unsigned)total);
            s_prefix = 0;
        } else {
            atomicExch(&g_state[bid], (1ULL << 62) | (unsigned)total);
            int run = 0;
            int j = bid - 1;
            while (true) {
                unsigned long long v = atomicAdd(&g_state[j], 0ULL);
                unsigned f = (unsigned)(v >> 62);
                if (f == 0) { __nanosleep(20); continue; }
                run += (int)(v & 0xFFFFFFFFULL);
                if (f == 2) break;
                j--;
            }
            atomicExch(&g_state[bid], (2ULL << 62) | (unsigned)(run + total));
            s_prefix = run;
        }
    }
    __syncthreads();
    if (gid < N_NODES) {
        int o = s_prefix + wofs + incl - x;
        g_off[gid] = o;
        g_cursor[gid] = o;
    }
}

// ---------------------------------------------------------------------------
// Scatter: ex = exp(leaky(s_src[s]+s_dst[d]+b)); place {src,ex} dst-sorted.
// (1 edge/thread, separate cursor array: the known-good configuration.)
// ---------------------------------------------------------------------------
__global__ void k_scatter(const int* __restrict__ src, const int* __restrict__ dst,
                          const float* __restrict__ attnb)
{
    int e = blockIdx.x * blockDim.x + threadIdx.x;
    if (e >= N_EDGES) return;
    int s = src[e], d = dst[e];
    float v = g_ssrc[s] + g_sdst[d] + attnb[0];
    v = (v > 0.0f) ? v : 0.2f * v;
    float ex = __expf(v);
    int pos = atomicAdd(&g_cursor[d], 1);
    unsigned long long p =
        ((unsigned long long)(unsigned)s << 32) | (unsigned long long)__float_as_uint(ex);
    g_edge[pos] = p;
}

// ---------------------------------------------------------------------------
// Gather: 16 threads/node = two 8-lane groups splitting the edge list
// (even/odd interleave). Each lane owns 6 outputs (3 x u32 fp16 pairs per
// edge, as in the best-known R3 layout). Halves the serial dependent chain
// and warp-tail imbalance; partial sums combined with one shfl_xor(8).
// ---------------------------------------------------------------------------
__device__ __forceinline__ void acc6(float* a, unsigned w0, unsigned w1, unsigned w2, float ex)
{
    float2 f;
    f = __half22float2(*(__half2*)&w0); a[0] = fmaf(f.x, ex, a[0]); a[1] = fmaf(f.y, ex, a[1]);
    f = __half22float2(*(__half2*)&w1); a[2] = fmaf(f.x, ex, a[2]); a[3] = fmaf(f.y, ex, a[3]);
    f = __half22float2(*(__half2*)&w2); a[4] = fmaf(f.x, ex, a[4]); a[5] = fmaf(f.y, ex, a[5]);
}

__global__ void __launch_bounds__(256) k_gather(float* __restrict__ out)
{
    int gt = blockIdx.x * blockDim.x + threadIdx.x;
    int n = gt >> 4;
    int t = gt & 15;           // 16 lanes per node (contiguous in the warp)
    if (n >= N_NODES) return;
    int start = g_off[n];
    int deg = g_cnt[n];
    int grp = t >> 3;          // 0: even edges, 1: odd edges
    int tt = t & 7;            // lane within group

    const unsigned* H = (const unsigned*)g_hh;  // row = 24 u32 (96B)
    int hb = tt * 3;

    float a[6] = {0.f, 0.f, 0.f, 0.f, 0.f, 0.f};
    float den = 0.0f;

    int k = grp;
    // 2-edge unroll over this group's strided (step 2) edge list
    for (; k + 2 < deg; k += 4) {
        unsigned long long p0 = g_edge[start + k];
        unsigned long long p1 = g_edge[start + k + 2];
        float ex0 = __uint_as_float((unsigned)p0);
        float ex1 = __uint_as_float((unsigned)p1);
        int s0 = (int)(p0 >> 32), s1 = (int)(p1 >> 32);
        const unsigned* h0 = H + s0 * 24 + hb;
        const unsigned* h1 = H + s1 * 24 + hb;
        unsigned w00 = h0[0], w01 = h0[1], w02 = h0[2];
        unsigned w10 = h1[0], w11 = h1[1], w12 = h1[2];
        den += ex0 + ex1;
        acc6(a, w00, w01, w02, ex0);
        acc6(a, w10, w11, w12, ex1);
    }
    if (k < deg) {
        unsigned long long p0 = g_edge[start + k];
        float ex0 = __uint_as_float((unsigned)p0);
        int s0 = (int)(p0 >> 32);
        const unsigned* h0 = H + s0 * 24 + hb;
        unsigned w00 = h0[0], w01 = h0[1], w02 = h0[2];
        den += ex0;
        acc6(a, w00, w01, w02, ex0);
    }

    // Combine the two groups (lanes differ in bit 3 of the lane id)
#pragma unroll
    for (int i = 0; i < 6; i++) a[i] += __shfl_xor_sync(0xFFFFFFFFu, a[i], 8);
    den += __shfl_xor_sync(0xFFFFFFFFu, den, 8);

    if (grp == 0) {
        float inv = (deg > 0) ? 1.0f / den : 0.0f;
        float2* op = (float2*)(out + (size_t)n * OUT_F + tt * 6);
        op[0] = make_float2(a[0] * inv, a[1] * inv);
        op[1] = make_float2(a[2] * inv, a[3] * inv);
        op[2] = make_float2(a[4] * inv, a[5] * inv);
    }
    // Restore zero-invariants for the next graph replay (warp-safe: the
    // g_cnt load above is issued for the whole warp before any lane stores).
    if (t == 8) g_cnt[n] = 0;
    if (t == 9 && n < NBLK_SCAN) g_state[n] = 0ULL;
}

// ---------------------------------------------------------------------------
extern "C" void kernel_launch(void* const* d_in, const int* in_sizes, int n_in,
                              void* d_out, int out_size)
{
    const float* feat  = (const float*)d_in[0];
    const float* Ww    = (const float*)d_in[1];
    const float* Wb    = (const float*)d_in[2];
    const float* attnw = (const float*)d_in[3];
    const float* attnb = (const float*)d_in[4];
    const int*   src   = (const int*)d_in[5];
    const int*   dst   = (const int*)d_in[6];
    float* out = (float*)d_out;

    k_gemm<<<(N_NODES + 255) / 256, 128>>>(feat, Ww, Wb, attnw, dst);
    k_scan<<<NBLK_SCAN, 1024>>>();
    k_scatter<<<(N_EDGES + 255) / 256, 256>>>(src, dst, attnb);
    k_gather<<<(N_NODES * 16 + 255) / 256, 256>>>(out);
}